// round 7
// baseline (speedup 1.0000x reference)
#include <cuda_runtime.h>
#include <math.h>

#define NVERT 289
#define NFACE 512
#define IMGS  128
#define KF    8
#define MAXC  224
#define NTH   512

#define KEY_INVALID 0xFFFFFFFFFFFFFFFFull

// ---------------------------------------------------------------------------
// Face connectivity: replicate _build_faces(17,17) analytically.
// ---------------------------------------------------------------------------
__device__ __forceinline__ void face_vids(int f, int& i0, int& i1, int& i2) {
    int grp = f >> 6;
    int g   = f & 63;
    int nyi = g >> 3;
    int nxi = g & 7;
    int ny = (grp >= 4) ? (1 + 2 * nyi) : (2 * nyi);
    int nx;
    if (grp == 0 || grp == 1 || grp == 6 || grp == 7) nx = 1 + 2 * nxi;
    else                                              nx = 2 * nxi;
    int a  = ny * 17 + nx;
    int r  = a + 1;
    int d  = a + 17;
    int dr = a + 18;
    switch (grp) {
        case 0: i0 = r;  i1 = a; i2 = d;  break;
        case 1: i0 = r;  i1 = d; i2 = dr; break;
        case 2: i0 = r;  i1 = a; i2 = dr; break;
        case 3: i0 = dr; i1 = a; i2 = d;  break;
        case 4: i0 = r;  i1 = a; i2 = d;  break;
        case 5: i0 = r;  i1 = d; i2 = dr; break;
        case 6: i0 = r;  i1 = a; i2 = dr; break;
        default:i0 = dr; i1 = a; i2 = d;  break;
    }
}

__device__ __forceinline__ float seg_d2_fast(float px, float py,
                                             float sx, float sy,
                                             float ex, float ey, float invL) {
    float dx = ex - sx, dy = ey - sy;
    float t = ((px - sx) * dx + (py - sy) * dy) * invL;
    t = fminf(fmaxf(t, 0.0f), 1.0f);
    float ux = px - (sx + t * dx);
    float uy = py - (sy + t * dy);
    return ux * ux + uy * uy;
}

__device__ __forceinline__ bool eval_face(float px, float py,
                                          float4 A, float4 B, float4 C, float4 E,
                                          float& sdist, float& zpix,
                                          float& bn0, float& bn1, float& bn2) {
    float ax = A.x, ay = A.y, z0 = A.z, inv_area = A.w;
    float bx = B.x, by = B.y, z1 = B.z, invLab = B.w;
    float cx = C.x, cy = C.y, z2 = C.z, invLbc = C.w;
    float invLca = E.x, z1z2 = E.y, z0z2 = E.z, z0z1 = E.w;

    float w0 = (bx - px) * (cy - py) - (by - py) * (cx - px);
    float w1 = (cx - px) * (ay - py) - (cy - py) * (ax - px);
    float w2 = (ax - px) * (by - py) - (ay - py) * (bx - px);

    float b0 = w0 * inv_area, b1 = w1 * inv_area, b2 = w2 * inv_area;
    bool inside = (b0 >= 0.0f) && (b1 >= 0.0f) && (b2 >= 0.0f);

    float n0 = b0 * z1z2;
    float n1 = b1 * z0z2;
    float n2 = b2 * z0z1;
    float den = n0 + n1 + n2;
    den = (fabsf(den) < 1e-10f) ? 1e-10f : den;
    float rden = __frcp_rn(den);
    float c0 = fmaxf(n0 * rden, 0.0f);
    float c1 = fmaxf(n1 * rden, 0.0f);
    float c2 = fmaxf(n2 * rden, 0.0f);
    float rsum = __frcp_rn(fmaxf(c0 + c1 + c2, 1e-10f));
    bn0 = c0 * rsum; bn1 = c1 * rsum; bn2 = c2 * rsum;
    zpix = bn0 * z0 + bn1 * z1 + bn2 * z2;

    float d2 = fminf(fminf(seg_d2_fast(px, py, ax, ay, bx, by, invLab),
                           seg_d2_fast(px, py, bx, by, cx, cy, invLbc)),
                     seg_d2_fast(px, py, cx, cy, ax, ay, invLca));
    sdist = inside ? -d2 : d2;
    return (sdist < 1e-4f) && (zpix > 1e-4f);
}

__device__ __forceinline__ unsigned long long u64min(unsigned long long a,
                                                     unsigned long long b) {
    return (a < b) ? a : b;
}

__global__ void __launch_bounds__(NTH)
nvp_kernel(const float* __restrict__ xy_off,
           const float* __restrict__ z_grid,
           const float* __restrict__ tex,
           const float* __restrict__ R_in,
           const float* __restrict__ T_in,
           const float* __restrict__ R_out,
           const float* __restrict__ T_out,
           float* __restrict__ out) {
    __shared__ float  s_vx[NVERT], s_vy[NVERT], s_vz[NVERT];
    __shared__ float2 s_bx[MAXC];
    __shared__ float4 s_A[MAXC], s_B[MAXC], s_C[MAXC], s_E[MAXC];
    __shared__ int4   s_vi[MAXC];
    __shared__ int    s_wc[16];

    const int tid  = threadIdx.x;
    const int lane = tid & 31;
    const int wid  = tid >> 5;
    const int sub  = tid & 7;               // lane within pixel octet
    const int pixb = tid >> 3;              // pixel within block (0..63)
    const int bxh  = blockIdx.x & 1;        // x half
    const int iy   = blockIdx.x >> 1;
    const int ix   = bxh * 64 + pixb;
    const float px = 1.0f - (float)(2 * ix + 1) * 0.0078125f;
    const float py = 1.0f - (float)(2 * iy + 1) * 0.0078125f;
    const int ix0  = bxh * 64;
    const float pxhi = 1.0f - (float)(2 * ix0 + 1) * 0.0078125f;
    const float pxlo = 1.0f - (float)(2 * (ix0 + 63) + 1) * 0.0078125f;

    // --- vertex transform (one pass) ---
    if (tid < NVERT) {
        float ri[9], ro[9], ti[3], to[3];
#pragma unroll
        for (int i = 0; i < 9; i++) { ri[i] = __ldg(R_in + i); ro[i] = __ldg(R_out + i); }
#pragma unroll
        for (int i = 0; i < 3; i++) { ti[i] = __ldg(T_in + i); to[i] = __ldg(T_out + i); }
        const float SCALE = 0.57735026918962576451f;   // tan(30deg)
        const float SINV  = 1.7320508075688772935f;    // 1/SCALE
        int v = tid;
        float xs = -1.0f + (float)(v % 17) * 0.125f;
        float ys = -1.0f + (float)(v / 17) * 0.125f;
        float gx = (xs + __ldg(xy_off + 2 * v)) * SCALE;
        float gy = (ys + __ldg(xy_off + 2 * v + 1)) * SCALE;
        float zg = __ldg(z_grid + v);
        float sx = gx * zg, sy = gy * zg, sz = zg;
        float p0 = sx - ti[0], p1 = sy - ti[1], p2 = sz - ti[2];
        float w0 = ri[0] * p0 + ri[1] * p1 + ri[2] * p2;
        float w1 = ri[3] * p0 + ri[4] * p1 + ri[5] * p2;
        float w2 = ri[6] * p0 + ri[7] * p1 + ri[8] * p2;
        float vx = ro[0] * w0 + ro[3] * w1 + ro[6] * w2 + to[0];
        float vy = ro[1] * w0 + ro[4] * w1 + ro[7] * w2 + to[1];
        float vz = ro[2] * w0 + ro[5] * w1 + ro[8] * w2 + to[2];
        float zden = (vz >= 0.0f) ? fmaxf(vz, 0.01f) : fminf(vz, -0.01f);
        s_vx[v] = SINV * vx / zden;
        s_vy[v] = SINV * vy / zden;
        s_vz[v] = vz;
    }
    __syncthreads();

    // --- face setup + single-round order-preserving (y AND block-x) compaction ---
    const float M = 0.0105f;
    int total = 0;
    {
        int f = tid;  // NTH == NFACE
        int i0, i1, i2;
        face_vids(f, i0, i1, i2);
        float ax = s_vx[i0], ay = s_vy[i0], z0 = s_vz[i0];
        float bx = s_vx[i1], by = s_vy[i1], z1 = s_vz[i1];
        float cx = s_vx[i2], cy = s_vy[i2], z2 = s_vz[i2];
        float ymn = fminf(ay, fminf(by, cy)) - M;
        float ymx = fmaxf(ay, fmaxf(by, cy)) + M;
        float xmn = fminf(ax, fminf(bx, cx)) - M;
        float xmx = fmaxf(ax, fmaxf(bx, cx)) + M;
        bool ov = (py >= ymn) && (py <= ymx) && (xmn <= pxhi) && (xmx >= pxlo);

        unsigned m = __ballot_sync(0xffffffffu, ov);
        if (lane == 0) s_wc[wid] = __popc(m);
        __syncthreads();
        int pos = __popc(m & ((1u << lane) - 1u));
#pragma unroll
        for (int w = 0; w < 16; w++) {
            if (w < wid) pos += s_wc[w];
            total += s_wc[w];
        }
        if (ov && pos < MAXC) {
            float area = (bx - ax) * (cy - ay) - (by - ay) * (cx - ax);
            float area_s = (fabsf(area) < 1e-8f) ? 1e-8f : area;
            float dabx = bx - ax, daby = by - ay;
            float dbcx = cx - bx, dbcy = cy - by;
            float dcax = ax - cx, dcay = ay - cy;
            float Lab = fmaxf(dabx * dabx + daby * daby, 1e-12f);
            float Lbc = fmaxf(dbcx * dbcx + dbcy * dbcy, 1e-12f);
            float Lca = fmaxf(dcax * dcax + dcay * dcay, 1e-12f);
            s_bx[pos] = make_float2(xmn, xmx);
            s_A[pos]  = make_float4(ax, ay, z0, 1.0f / area_s);
            s_B[pos]  = make_float4(bx, by, z1, 1.0f / Lab);
            s_C[pos]  = make_float4(cx, cy, z2, 1.0f / Lbc);
            s_E[pos]  = make_float4(1.0f / Lca, z1 * z2, z0 * z2, z0 * z1);
            s_vi[pos] = make_int4(i0, i1, i2, 0);
        }
        __syncthreads();
    }
    if (total > MAXC) total = MAXC;

    // --- selection: 8-way strided, packed u64 keys (z_bits<<32 | idx) ---
    unsigned long long kk[KF];
#pragma unroll
    for (int k = 0; k < KF; k++) kk[k] = KEY_INVALID;

#pragma unroll 2
    for (int i = sub; i < total; i += 8) {
        float2 bb = s_bx[i];
        if (px < bb.x || px > bb.y) continue;
        float sdist, zpix, bn0, bn1, bn2;
        bool valid = eval_face(px, py, s_A[i], s_B[i], s_C[i], s_E[i],
                               sdist, zpix, bn0, bn1, bn2);
        if (valid) {
            unsigned long long key =
                ((unsigned long long)__float_as_uint(zpix) << 32) | (unsigned)i;
            if (key < kk[KF - 1]) {
#pragma unroll
                for (int j = 0; j < KF; j++) {
                    if (key < kk[j]) {
                        unsigned long long t = kk[j]; kk[j] = key; key = t;
                    }
                }
            }
        }
    }

    // --- merge 8 per-lane sorted top-8 lists: 3 full rounds (xor 1, 2, 4) ---
    // Each round: symmetric min-merge then bitonic cleanup, leaving every lane
    // with an identical fully-sorted top-8 list. (Skipping the last cleanup is
    // invalid: partner lanes end up with reversed copies and the octet then
    // shades half the set twice -> softmax underflow -> NaN.)
#pragma unroll
    for (int d = 1; d <= 4; d <<= 1) {
        unsigned long long bk[KF];
#pragma unroll
        for (int i = 0; i < KF; i++)
            bk[i] = __shfl_xor_sync(0xffffffffu, kk[i], d);
        unsigned long long ck[KF];
#pragma unroll
        for (int i = 0; i < KF; i++)
            ck[i] = u64min(kk[i], bk[KF - 1 - i]);
#pragma unroll
        for (int d2 = 4; d2 >= 1; d2 >>= 1) {
#pragma unroll
            for (int i = 0; i < KF; i++) {
                if ((i & d2) == 0) {
                    int j = i + d2;
                    unsigned long long lo = u64min(ck[i], ck[j]);
                    unsigned long long hi = (ck[i] < ck[j]) ? ck[j] : ck[i];
                    ck[i] = lo; ck[j] = hi;
                }
            }
        }
#pragma unroll
        for (int i = 0; i < KF; i++) kk[i] = ck[i];
    }

    // --- softmax prep (all lanes hold identical sorted lists) ---
    const float R99 = 0.010101010101010102f;
    float zmax = 1e-10f;
#pragma unroll
    for (int k = 0; k < KF; k++) {
        unsigned zb = (unsigned)(kk[k] >> 32);
        float zi = (zb != 0xFFFFFFFFu) ? (100.0f - __uint_as_float(zb)) * R99 : 0.0f;
        zmax = fmaxf(zmax, zi);
    }
    float delta = __expf((1e-10f - zmax) * 1e4f);

    // --- shading: lane `sub` shades element kk[sub] (static 8-way select) ---
    unsigned long long ksel = kk[0];
    if (sub == 1) ksel = kk[1];
    if (sub == 2) ksel = kk[2];
    if (sub == 3) ksel = kk[3];
    if (sub == 4) ksel = kk[4];
    if (sub == 5) ksel = kk[5];
    if (sub == 6) ksel = kk[6];
    if (sub == 7) ksel = kk[7];

    float sw = 0.0f, sr = 0.0f, sg = 0.0f, sb = 0.0f, sd = 0.0f, ap = 1.0f;
    {
        unsigned zb = (unsigned)(ksel >> 32);
        if (zb != 0xFFFFFFFFu) {
            int f = (int)(unsigned)ksel;
            float zsel = __uint_as_float(zb);
            float sdist, zpix, bn0, bn1, bn2;
            eval_face(px, py, s_A[f], s_B[f], s_C[f], s_E[f], sdist, zpix, bn0, bn1, bn2);
            int4 vi = s_vi[f];
            float u0 = 1.0f - (float)(vi.x % 17) * 0.0625f, vc0 = (float)(vi.x / 17) * 0.0625f;
            float u1 = 1.0f - (float)(vi.y % 17) * 0.0625f, vc1 = (float)(vi.y / 17) * 0.0625f;
            float u2 = 1.0f - (float)(vi.z % 17) * 0.0625f, vc2 = (float)(vi.z / 17) * 0.0625f;
            float uu = bn0 * u0 + bn1 * u1 + bn2 * u2;
            float vv = bn0 * vc0 + bn1 * vc1 + bn2 * vc2;
            float tx = uu * 127.0f;
            float ty = (1.0f - vv) * 127.0f;
            float x0f = fminf(fmaxf(floorf(tx), 0.0f), 127.0f);
            float y0f = fminf(fmaxf(floorf(ty), 0.0f), 127.0f);
            int x0 = (int)x0f, y0 = (int)y0f;
            int x1 = min(x0 + 1, 127), y1 = min(y0 + 1, 127);
            float wx = tx - x0f, wy = ty - y0f;
            const float* p00 = tex + (y0 * IMGS + x0) * 3;
            const float* p01 = tex + (y0 * IMGS + x1) * 3;
            const float* p10 = tex + (y1 * IMGS + x0) * 3;
            const float* p11 = tex + (y1 * IMGS + x1) * 3;
            float omwx = 1.0f - wx, omwy = 1.0f - wy;
            float cr = omwy * (omwx * __ldg(p00 + 0) + wx * __ldg(p01 + 0)) +
                       wy   * (omwx * __ldg(p10 + 0) + wx * __ldg(p11 + 0));
            float cg = omwy * (omwx * __ldg(p00 + 1) + wx * __ldg(p01 + 1)) +
                       wy   * (omwx * __ldg(p10 + 1) + wx * __ldg(p11 + 1));
            float cb = omwy * (omwx * __ldg(p00 + 2) + wx * __ldg(p01 + 2)) +
                       wy   * (omwx * __ldg(p10 + 2) + wx * __ldg(p11 + 2));
            float pr  = __frcp_rn(1.0f + __expf(sdist * 1e4f));
            float zin = (100.0f - zsel) * R99;
            float w   = pr * __expf((zin - zmax) * 1e4f);
            sw = w;
            sr = w * cr;
            sg = w * cg;
            sb = w * cb;
            sd = w * zsel;
            ap = 1.0f - pr;
        }
    }

    // --- octet butterfly reduction ---
#pragma unroll
    for (int d = 1; d <= 4; d <<= 1) {
        sw += __shfl_xor_sync(0xffffffffu, sw, d);
        sr += __shfl_xor_sync(0xffffffffu, sr, d);
        sg += __shfl_xor_sync(0xffffffffu, sg, d);
        sb += __shfl_xor_sync(0xffffffffu, sb, d);
        sd += __shfl_xor_sync(0xffffffffu, sd, d);
        ap *= __shfl_xor_sync(0xffffffffu, ap, d);
    }
    float rdenom = __frcp_rn(sw + delta);

    int o = (iy * IMGS + ix) * 5;
    if (sub == 0) out[o + 0] = sr * rdenom;
    else if (sub == 1) out[o + 1] = sg * rdenom;
    else if (sub == 2) out[o + 2] = sb * rdenom;
    else if (sub == 3) out[o + 3] = 1.0f - ap;
    else if (sub == 4) out[o + 4] = (sd + delta * 100.0f) * rdenom;
}

extern "C" void kernel_launch(void* const* d_in, const int* in_sizes, int n_in,
                              void* d_out, int out_size) {
    (void)in_sizes; (void)n_in; (void)out_size;
    nvp_kernel<<<IMGS * 2, NTH>>>(
        (const float*)d_in[0],   // xy_offset (1,289,2)
        (const float*)d_in[1],   // z_grid    (1,289,1)
        (const float*)d_in[2],   // rgb_in    (1,128,128,3)
        (const float*)d_in[3],   // R_in      (1,3,3)
        (const float*)d_in[4],   // T_in      (1,3)
        (const float*)d_in[5],   // R_out     (1,3,3)
        (const float*)d_in[6],   // T_out     (1,3)
        (float*)d_out);          // (1,128,128,5) float32
}

// round 8
// speedup vs baseline: 1.3653x; 1.3653x over previous
#include <cuda_runtime.h>
#include <math.h>

#define NVERT 289
#define NFACE 512
#define IMGS  128
#define KF    8
#define MAXC  128
#define NTH   256

#define KEY_INVALID 0xFFFFFFFFFFFFFFFFull

// ---------------------------------------------------------------------------
// Face connectivity: replicate _build_faces(17,17) analytically.
// ---------------------------------------------------------------------------
__device__ __forceinline__ void face_vids(int f, int& i0, int& i1, int& i2) {
    int grp = f >> 6;
    int g   = f & 63;
    int nyi = g >> 3;
    int nxi = g & 7;
    int ny = (grp >= 4) ? (1 + 2 * nyi) : (2 * nyi);
    int nx;
    if (grp == 0 || grp == 1 || grp == 6 || grp == 7) nx = 1 + 2 * nxi;
    else                                              nx = 2 * nxi;
    int a  = ny * 17 + nx;
    int r  = a + 1;
    int d  = a + 17;
    int dr = a + 18;
    switch (grp) {
        case 0: i0 = r;  i1 = a; i2 = d;  break;
        case 1: i0 = r;  i1 = d; i2 = dr; break;
        case 2: i0 = r;  i1 = a; i2 = dr; break;
        case 3: i0 = dr; i1 = a; i2 = d;  break;
        case 4: i0 = r;  i1 = a; i2 = d;  break;
        case 5: i0 = r;  i1 = d; i2 = dr; break;
        case 6: i0 = r;  i1 = a; i2 = dr; break;
        default:i0 = dr; i1 = a; i2 = d;  break;
    }
}

__device__ __forceinline__ float seg_d2_fast(float px, float py,
                                             float sx, float sy,
                                             float ex, float ey, float invL) {
    float dx = ex - sx, dy = ey - sy;
    float t = ((px - sx) * dx + (py - sy) * dy) * invL;
    t = fminf(fmaxf(t, 0.0f), 1.0f);
    float ux = px - (sx + t * dx);
    float uy = py - (sy + t * dy);
    return ux * ux + uy * uy;
}

__device__ __forceinline__ bool eval_face(float px, float py,
                                          float4 A, float4 B, float4 C, float4 E,
                                          float& sdist, float& zpix,
                                          float& bn0, float& bn1, float& bn2) {
    float ax = A.x, ay = A.y, z0 = A.z, inv_area = A.w;
    float bx = B.x, by = B.y, z1 = B.z, invLab = B.w;
    float cx = C.x, cy = C.y, z2 = C.z, invLbc = C.w;
    float invLca = E.x, z1z2 = E.y, z0z2 = E.z, z0z1 = E.w;

    float w0 = (bx - px) * (cy - py) - (by - py) * (cx - px);
    float w1 = (cx - px) * (ay - py) - (cy - py) * (ax - px);
    float w2 = (ax - px) * (by - py) - (ay - py) * (bx - px);

    float b0 = w0 * inv_area, b1 = w1 * inv_area, b2 = w2 * inv_area;
    bool inside = (b0 >= 0.0f) && (b1 >= 0.0f) && (b2 >= 0.0f);

    float n0 = b0 * z1z2;
    float n1 = b1 * z0z2;
    float n2 = b2 * z0z1;
    float den = n0 + n1 + n2;
    den = (fabsf(den) < 1e-10f) ? 1e-10f : den;
    float rden = __frcp_rn(den);
    float c0 = fmaxf(n0 * rden, 0.0f);
    float c1 = fmaxf(n1 * rden, 0.0f);
    float c2 = fmaxf(n2 * rden, 0.0f);
    float rsum = __frcp_rn(fmaxf(c0 + c1 + c2, 1e-10f));
    bn0 = c0 * rsum; bn1 = c1 * rsum; bn2 = c2 * rsum;
    zpix = bn0 * z0 + bn1 * z1 + bn2 * z2;

    float d2 = fminf(fminf(seg_d2_fast(px, py, ax, ay, bx, by, invLab),
                           seg_d2_fast(px, py, bx, by, cx, cy, invLbc)),
                     seg_d2_fast(px, py, cx, cy, ax, ay, invLca));
    sdist = inside ? -d2 : d2;
    return (sdist < 1e-4f) && (zpix > 1e-4f);
}

__device__ __forceinline__ unsigned long long u64min(unsigned long long a,
                                                     unsigned long long b) {
    return (a < b) ? a : b;
}

__global__ void __launch_bounds__(NTH)
nvp_kernel(const float* __restrict__ xy_off,
           const float* __restrict__ z_grid,
           const float* __restrict__ tex,
           const float* __restrict__ R_in,
           const float* __restrict__ T_in,
           const float* __restrict__ R_out,
           const float* __restrict__ T_out,
           float* __restrict__ out) {
    __shared__ float  s_vx[NVERT], s_vy[NVERT], s_vz[NVERT];
    __shared__ float4 s_bb[MAXC];                 // xmin,xmax,ymin,ymax
    __shared__ float4 s_A[MAXC], s_B[MAXC], s_C[MAXC], s_E[MAXC];
    __shared__ int4   s_vi[MAXC];
    __shared__ int    s_wc[8];

    const int tid  = threadIdx.x;
    const int lane = tid & 31;
    const int wid  = tid >> 5;
    const int sub  = tid & 3;               // lane within pixel quad
    const int pixb = tid >> 2;              // pixel within tile (0..63)
    const int tx   = blockIdx.x & 15;       // 16x16 tiles of 8x8 px
    const int ty   = blockIdx.x >> 4;
    const int ix   = tx * 8 + (pixb & 7);
    const int iy   = ty * 8 + (pixb >> 3);
    const float px = 1.0f - (float)(2 * ix + 1) * 0.0078125f;
    const float py = 1.0f - (float)(2 * iy + 1) * 0.0078125f;
    // NDC extents of this tile (px,py decrease with ix,iy)
    const float pxhi = 1.0f - (float)(2 * (tx * 8) + 1) * 0.0078125f;
    const float pxlo = 1.0f - (float)(2 * (tx * 8 + 7) + 1) * 0.0078125f;
    const float pyhi = 1.0f - (float)(2 * (ty * 8) + 1) * 0.0078125f;
    const float pylo = 1.0f - (float)(2 * (ty * 8 + 7) + 1) * 0.0078125f;

    // --- vertex transform ---
    {
        float ri[9], ro[9], ti[3], to[3];
#pragma unroll
        for (int i = 0; i < 9; i++) { ri[i] = __ldg(R_in + i); ro[i] = __ldg(R_out + i); }
#pragma unroll
        for (int i = 0; i < 3; i++) { ti[i] = __ldg(T_in + i); to[i] = __ldg(T_out + i); }
        const float SCALE = 0.57735026918962576451f;   // tan(30deg)
        const float SINV  = 1.7320508075688772935f;    // 1/SCALE
        for (int v = tid; v < NVERT; v += NTH) {
            float xs = -1.0f + (float)(v % 17) * 0.125f;
            float ys = -1.0f + (float)(v / 17) * 0.125f;
            float gx = (xs + __ldg(xy_off + 2 * v)) * SCALE;
            float gy = (ys + __ldg(xy_off + 2 * v + 1)) * SCALE;
            float zg = __ldg(z_grid + v);
            float sx = gx * zg, sy = gy * zg, sz = zg;
            float p0 = sx - ti[0], p1 = sy - ti[1], p2 = sz - ti[2];
            float w0 = ri[0] * p0 + ri[1] * p1 + ri[2] * p2;
            float w1 = ri[3] * p0 + ri[4] * p1 + ri[5] * p2;
            float w2 = ri[6] * p0 + ri[7] * p1 + ri[8] * p2;
            float vx = ro[0] * w0 + ro[3] * w1 + ro[6] * w2 + to[0];
            float vy = ro[1] * w0 + ro[4] * w1 + ro[7] * w2 + to[1];
            float vz = ro[2] * w0 + ro[5] * w1 + ro[8] * w2 + to[2];
            float zden = (vz >= 0.0f) ? fmaxf(vz, 0.01f) : fminf(vz, -0.01f);
            s_vx[v] = SINV * vx / zden;
            s_vy[v] = SINV * vy / zden;
            s_vz[v] = vz;
        }
    }
    __syncthreads();

    // --- face setup + order-preserving tile (x AND y) compaction ---
    const float M = 0.0105f;   // blur reach sqrt(1e-4)=0.01 + fp margin
    int total = 0;
#pragma unroll
    for (int c = 0; c < 2; c++) {
        int f = c * NTH + tid;
        int i0, i1, i2;
        face_vids(f, i0, i1, i2);
        float ax = s_vx[i0], ay = s_vy[i0], z0 = s_vz[i0];
        float bx = s_vx[i1], by = s_vy[i1], z1 = s_vz[i1];
        float cx = s_vx[i2], cy = s_vy[i2], z2 = s_vz[i2];
        float ymn = fminf(ay, fminf(by, cy)) - M;
        float ymx = fmaxf(ay, fmaxf(by, cy)) + M;
        float xmn = fminf(ax, fminf(bx, cx)) - M;
        float xmx = fmaxf(ax, fmaxf(bx, cx)) + M;
        bool ov = (xmn <= pxhi) && (xmx >= pxlo) && (ymn <= pyhi) && (ymx >= pylo);

        unsigned m = __ballot_sync(0xffffffffu, ov);
        if (lane == 0) s_wc[wid] = __popc(m);
        __syncthreads();
        int pos = total + __popc(m & ((1u << lane) - 1u));
#pragma unroll
        for (int w = 0; w < 8; w++) {
            if (w < wid) pos += s_wc[w];
            total += s_wc[w];
        }
        if (ov && pos < MAXC) {
            float area = (bx - ax) * (cy - ay) - (by - ay) * (cx - ax);
            float area_s = (fabsf(area) < 1e-8f) ? 1e-8f : area;
            float dabx = bx - ax, daby = by - ay;
            float dbcx = cx - bx, dbcy = cy - by;
            float dcax = ax - cx, dcay = ay - cy;
            float Lab = fmaxf(dabx * dabx + daby * daby, 1e-12f);
            float Lbc = fmaxf(dbcx * dbcx + dbcy * dbcy, 1e-12f);
            float Lca = fmaxf(dcax * dcax + dcay * dcay, 1e-12f);
            s_bb[pos] = make_float4(xmn, xmx, ymn, ymx);
            s_A[pos]  = make_float4(ax, ay, z0, 1.0f / area_s);
            s_B[pos]  = make_float4(bx, by, z1, 1.0f / Lab);
            s_C[pos]  = make_float4(cx, cy, z2, 1.0f / Lbc);
            s_E[pos]  = make_float4(1.0f / Lca, z1 * z2, z0 * z2, z0 * z1);
            s_vi[pos] = make_int4(i0, i1, i2, 0);
        }
        __syncthreads();
    }
    if (total > MAXC) total = MAXC;

    // --- selection: 4-way strided, packed u64 keys (z_bits<<32 | idx) ---
    unsigned long long kk[KF];
#pragma unroll
    for (int k = 0; k < KF; k++) kk[k] = KEY_INVALID;

    for (int i = sub; i < total; i += 4) {
        float4 bb = s_bb[i];
        if (px < bb.x || px > bb.y || py < bb.z || py > bb.w) continue;
        float sdist, zpix, bn0, bn1, bn2;
        bool valid = eval_face(px, py, s_A[i], s_B[i], s_C[i], s_E[i],
                               sdist, zpix, bn0, bn1, bn2);
        if (valid) {
            unsigned long long key =
                ((unsigned long long)__float_as_uint(zpix) << 32) | (unsigned)i;
            if (key < kk[KF - 1]) {
#pragma unroll
                for (int j = 0; j < KF; j++) {
                    if (key < kk[j]) {
                        unsigned long long t = kk[j]; kk[j] = key; key = t;
                    }
                }
            }
        }
    }

    // --- merge 4 per-lane sorted lists ---
    // Round 1 (xor 1): full merge + bitonic cleanup -> pair-identical sorted lists.
    {
        unsigned long long bk[KF];
#pragma unroll
        for (int i = 0; i < KF; i++)
            bk[i] = __shfl_xor_sync(0xffffffffu, kk[i], 1);
        unsigned long long ck[KF];
#pragma unroll
        for (int i = 0; i < KF; i++)
            ck[i] = u64min(kk[i], bk[KF - 1 - i]);
#pragma unroll
        for (int d2 = 4; d2 >= 1; d2 >>= 1) {
#pragma unroll
            for (int i = 0; i < KF; i++) {
                if ((i & d2) == 0) {
                    int j = i + d2;
                    unsigned long long lo = u64min(ck[i], ck[j]);
                    unsigned long long hi = (ck[i] < ck[j]) ? ck[j] : ck[i];
                    ck[i] = lo; ck[j] = hi;
                }
            }
        }
#pragma unroll
        for (int i = 0; i < KF; i++) kk[i] = ck[i];
    }
    // Round 2 (xor 2): min-merge ONLY. Lanes 0,1 hold the top-8 set X in bitonic
    // order; lanes 2,3 hold exactly reverse(X) (lane L^2 computes
    // min(B[i],A[7-i]) = lane L's element at index 7-i). Assignment below is
    // reversal-aware so each of the 8 set elements is shaded exactly once.
    {
        unsigned long long bk[KF];
#pragma unroll
        for (int i = 0; i < KF; i++)
            bk[i] = __shfl_xor_sync(0xffffffffu, kk[i], 2);
#pragma unroll
        for (int i = 0; i < KF; i++)
            kk[i] = u64min(kk[i], bk[KF - 1 - i]);
    }

    // --- softmax prep: set-max over local list (order-independent) ---
    const float R99 = 0.010101010101010102f;
    float zmax = 1e-10f;
#pragma unroll
    for (int k = 0; k < KF; k++) {
        unsigned zb = (unsigned)(kk[k] >> 32);
        float zi = (zb != 0xFFFFFFFFu) ? (100.0f - __uint_as_float(zb)) * R99 : 0.0f;
        zmax = fmaxf(zmax, zi);
    }
    float delta = __expf((1e-10f - zmax) * 1e4f);

    // --- reversal-aware assignment: lane0:{0,4} lane1:{1,5} lane2:{5,1} lane3:{4,0}
    unsigned long long ks[2];
    ks[0] = (sub == 0) ? kk[0] : (sub == 1) ? kk[1] : (sub == 2) ? kk[5] : kk[4];
    ks[1] = (sub == 0) ? kk[4] : (sub == 1) ? kk[5] : (sub == 2) ? kk[1] : kk[0];

    float sw = 0.0f, sr = 0.0f, sg = 0.0f, sb = 0.0f, sd = 0.0f, ap = 1.0f;
#pragma unroll
    for (int t = 0; t < 2; t++) {
        unsigned zb = (unsigned)(ks[t] >> 32);
        if (zb == 0xFFFFFFFFu) continue;
        int f = (int)(unsigned)ks[t];
        float zsel = __uint_as_float(zb);
        float sdist, zpix, bn0, bn1, bn2;
        eval_face(px, py, s_A[f], s_B[f], s_C[f], s_E[f], sdist, zpix, bn0, bn1, bn2);
        int4 vi = s_vi[f];
        float u0 = 1.0f - (float)(vi.x % 17) * 0.0625f, vc0 = (float)(vi.x / 17) * 0.0625f;
        float u1 = 1.0f - (float)(vi.y % 17) * 0.0625f, vc1 = (float)(vi.y / 17) * 0.0625f;
        float u2 = 1.0f - (float)(vi.z % 17) * 0.0625f, vc2 = (float)(vi.z / 17) * 0.0625f;
        float uu = bn0 * u0 + bn1 * u1 + bn2 * u2;
        float vv = bn0 * vc0 + bn1 * vc1 + bn2 * vc2;
        float tx2 = uu * 127.0f;
        float ty2 = (1.0f - vv) * 127.0f;
        float x0f = fminf(fmaxf(floorf(tx2), 0.0f), 127.0f);
        float y0f = fminf(fmaxf(floorf(ty2), 0.0f), 127.0f);
        int x0 = (int)x0f, y0 = (int)y0f;
        int x1 = min(x0 + 1, 127), y1 = min(y0 + 1, 127);
        float wx = tx2 - x0f, wy = ty2 - y0f;
        const float* p00 = tex + (y0 * IMGS + x0) * 3;
        const float* p01 = tex + (y0 * IMGS + x1) * 3;
        const float* p10 = tex + (y1 * IMGS + x0) * 3;
        const float* p11 = tex + (y1 * IMGS + x1) * 3;
        float omwx = 1.0f - wx, omwy = 1.0f - wy;
        float cr = omwy * (omwx * __ldg(p00 + 0) + wx * __ldg(p01 + 0)) +
                   wy   * (omwx * __ldg(p10 + 0) + wx * __ldg(p11 + 0));
        float cg = omwy * (omwx * __ldg(p00 + 1) + wx * __ldg(p01 + 1)) +
                   wy   * (omwx * __ldg(p10 + 1) + wx * __ldg(p11 + 1));
        float cb = omwy * (omwx * __ldg(p00 + 2) + wx * __ldg(p01 + 2)) +
                   wy   * (omwx * __ldg(p10 + 2) + wx * __ldg(p11 + 2));
        float pr  = __frcp_rn(1.0f + __expf(sdist * 1e4f));
        float zin = (100.0f - zsel) * R99;
        float w   = pr * __expf((zin - zmax) * 1e4f);
        sw += w;
        sr += w * cr;
        sg += w * cg;
        sb += w * cb;
        sd += w * zsel;
        ap *= (1.0f - pr);
    }

    // --- quad butterfly reduction ---
#pragma unroll
    for (int d = 1; d <= 2; d <<= 1) {
        sw += __shfl_xor_sync(0xffffffffu, sw, d);
        sr += __shfl_xor_sync(0xffffffffu, sr, d);
        sg += __shfl_xor_sync(0xffffffffu, sg, d);
        sb += __shfl_xor_sync(0xffffffffu, sb, d);
        sd += __shfl_xor_sync(0xffffffffu, sd, d);
        ap *= __shfl_xor_sync(0xffffffffu, ap, d);
    }
    float rdenom = __frcp_rn(sw + delta);

    int o = (iy * IMGS + ix) * 5;
    if (sub == 0) {
        out[o + 0] = sr * rdenom;
        out[o + 4] = (sd + delta * 100.0f) * rdenom;
    } else if (sub == 1) {
        out[o + 1] = sg * rdenom;
    } else if (sub == 2) {
        out[o + 2] = sb * rdenom;
    } else {
        out[o + 3] = 1.0f - ap;
    }
}

extern "C" void kernel_launch(void* const* d_in, const int* in_sizes, int n_in,
                              void* d_out, int out_size) {
    (void)in_sizes; (void)n_in; (void)out_size;
    nvp_kernel<<<256, NTH>>>(
        (const float*)d_in[0],   // xy_offset (1,289,2)
        (const float*)d_in[1],   // z_grid    (1,289,1)
        (const float*)d_in[2],   // rgb_in    (1,128,128,3)
        (const float*)d_in[3],   // R_in      (1,3,3)
        (const float*)d_in[4],   // T_in      (1,3)
        (const float*)d_in[5],   // R_out     (1,3,3)
        (const float*)d_in[6],   // T_out     (1,3)
        (float*)d_out);          // (1,128,128,5) float32
}

// round 9
// speedup vs baseline: 1.3688x; 1.0026x over previous
#include <cuda_runtime.h>
#include <math.h>

#define NVERT 289
#define NFACE 512
#define IMGS  128
#define KF    8
#define MAXC  128
#define NTH   256

#define KEY_INVALID 0xFFFFFFFFFFFFFFFFull

// ---------------------------------------------------------------------------
// Face connectivity: replicate _build_faces(17,17) analytically.
// ---------------------------------------------------------------------------
__device__ __forceinline__ void face_vids(int f, int& i0, int& i1, int& i2) {
    int grp = f >> 6;
    int g   = f & 63;
    int nyi = g >> 3;
    int nxi = g & 7;
    int ny = (grp >= 4) ? (1 + 2 * nyi) : (2 * nyi);
    int nx;
    if (grp == 0 || grp == 1 || grp == 6 || grp == 7) nx = 1 + 2 * nxi;
    else                                              nx = 2 * nxi;
    int a  = ny * 17 + nx;
    int r  = a + 1;
    int d  = a + 17;
    int dr = a + 18;
    switch (grp) {
        case 0: i0 = r;  i1 = a; i2 = d;  break;
        case 1: i0 = r;  i1 = d; i2 = dr; break;
        case 2: i0 = r;  i1 = a; i2 = dr; break;
        case 3: i0 = dr; i1 = a; i2 = d;  break;
        case 4: i0 = r;  i1 = a; i2 = d;  break;
        case 5: i0 = r;  i1 = d; i2 = dr; break;
        case 6: i0 = r;  i1 = a; i2 = dr; break;
        default:i0 = dr; i1 = a; i2 = d;  break;
    }
}

__device__ __forceinline__ float seg_d2_fast(float px, float py,
                                             float sx, float sy,
                                             float ex, float ey, float invL) {
    float dx = ex - sx, dy = ey - sy;
    float t = ((px - sx) * dx + (py - sy) * dy) * invL;
    t = fminf(fmaxf(t, 0.0f), 1.0f);
    float ux = px - (sx + t * dx);
    float uy = py - (sy + t * dy);
    return ux * ux + uy * uy;
}

// Selection-only eval: validity + zpix; seg_d2 computed lazily (outside only).
__device__ __forceinline__ bool eval_sel(float px, float py,
                                         float4 A, float4 B, float4 C, float4 E,
                                         float& zpix) {
    float ax = A.x, ay = A.y, z0 = A.z, inv_area = A.w;
    float bx = B.x, by = B.y, z1 = B.z, invLab = B.w;
    float cx = C.x, cy = C.y, z2 = C.z, invLbc = C.w;
    float invLca = E.x, z1z2 = E.y, z0z2 = E.z, z0z1 = E.w;

    float w0 = (bx - px) * (cy - py) - (by - py) * (cx - px);
    float w1 = (cx - px) * (ay - py) - (cy - py) * (ax - px);
    float w2 = (ax - px) * (by - py) - (ay - py) * (bx - px);

    float b0 = w0 * inv_area, b1 = w1 * inv_area, b2 = w2 * inv_area;
    bool inside = (b0 >= 0.0f) && (b1 >= 0.0f) && (b2 >= 0.0f);

    float n0 = b0 * z1z2;
    float n1 = b1 * z0z2;
    float n2 = b2 * z0z1;
    float den = n0 + n1 + n2;
    den = (fabsf(den) < 1e-10f) ? 1e-10f : den;
    float rden = __frcp_rn(den);
    float c0 = fmaxf(n0 * rden, 0.0f);
    float c1 = fmaxf(n1 * rden, 0.0f);
    float c2 = fmaxf(n2 * rden, 0.0f);
    float rsum = __frcp_rn(fmaxf(c0 + c1 + c2, 1e-10f));
    zpix = (c0 * z0 + c1 * z1 + c2 * z2) * rsum;

    if (zpix <= 1e-4f) return false;
    if (inside) return true;   // sdist = -d2 <= 0 < blur always
    float d2 = fminf(fminf(seg_d2_fast(px, py, ax, ay, bx, by, invLab),
                           seg_d2_fast(px, py, bx, by, cx, cy, invLbc)),
                     seg_d2_fast(px, py, cx, cy, ax, ay, invLca));
    return d2 < 1e-4f;
}

// Full eval (matches reference math) for shading.
__device__ __forceinline__ void eval_face(float px, float py,
                                          float4 A, float4 B, float4 C, float4 E,
                                          float& sdist, float& bn0, float& bn1, float& bn2) {
    float ax = A.x, ay = A.y, z0 = A.z, inv_area = A.w;
    float bx = B.x, by = B.y, z1 = B.z, invLab = B.w;
    float cx = C.x, cy = C.y, z2 = C.z, invLbc = C.w;
    float invLca = E.x, z1z2 = E.y, z0z2 = E.z, z0z1 = E.w;

    float w0 = (bx - px) * (cy - py) - (by - py) * (cx - px);
    float w1 = (cx - px) * (ay - py) - (cy - py) * (ax - px);
    float w2 = (ax - px) * (by - py) - (ay - py) * (bx - px);

    float b0 = w0 * inv_area, b1 = w1 * inv_area, b2 = w2 * inv_area;
    bool inside = (b0 >= 0.0f) && (b1 >= 0.0f) && (b2 >= 0.0f);

    float n0 = b0 * z1z2;
    float n1 = b1 * z0z2;
    float n2 = b2 * z0z1;
    float den = n0 + n1 + n2;
    den = (fabsf(den) < 1e-10f) ? 1e-10f : den;
    float rden = __frcp_rn(den);
    float c0 = fmaxf(n0 * rden, 0.0f);
    float c1 = fmaxf(n1 * rden, 0.0f);
    float c2 = fmaxf(n2 * rden, 0.0f);
    float rsum = __frcp_rn(fmaxf(c0 + c1 + c2, 1e-10f));
    bn0 = c0 * rsum; bn1 = c1 * rsum; bn2 = c2 * rsum;

    float d2 = fminf(fminf(seg_d2_fast(px, py, ax, ay, bx, by, invLab),
                           seg_d2_fast(px, py, bx, by, cx, cy, invLbc)),
                     seg_d2_fast(px, py, cx, cy, ax, ay, invLca));
    sdist = inside ? -d2 : d2;
}

__device__ __forceinline__ unsigned long long u64min(unsigned long long a,
                                                     unsigned long long b) {
    return (a < b) ? a : b;
}

__global__ void __launch_bounds__(NTH)
nvp_kernel(const float* __restrict__ xy_off,
           const float* __restrict__ z_grid,
           const float* __restrict__ tex,
           const float* __restrict__ R_in,
           const float* __restrict__ T_in,
           const float* __restrict__ R_out,
           const float* __restrict__ T_out,
           float* __restrict__ out) {
    __shared__ float  s_vx[NVERT], s_vy[NVERT], s_vz[NVERT];
    __shared__ float4 s_bb[MAXC];
    __shared__ float4 s_A[MAXC], s_B[MAXC], s_C[MAXC], s_E[MAXC];
    __shared__ int4   s_vi[MAXC];
    __shared__ int    s_wc[8];

    const int tid  = threadIdx.x;
    const int lane = tid & 31;
    const int wid  = tid >> 5;
    const int sub  = tid & 3;
    const int pixb = tid >> 2;
    const int tx   = blockIdx.x & 15;
    const int ty   = blockIdx.x >> 4;
    const int ix   = tx * 8 + (pixb & 7);
    const int iy   = ty * 8 + (pixb >> 3);
    const float px = 1.0f - (float)(2 * ix + 1) * 0.0078125f;
    const float py = 1.0f - (float)(2 * iy + 1) * 0.0078125f;
    const float pxhi = 1.0f - (float)(2 * (tx * 8) + 1) * 0.0078125f;
    const float pxlo = 1.0f - (float)(2 * (tx * 8 + 7) + 1) * 0.0078125f;
    const float pyhi = 1.0f - (float)(2 * (ty * 8) + 1) * 0.0078125f;
    const float pylo = 1.0f - (float)(2 * (ty * 8 + 7) + 1) * 0.0078125f;

    // --- vertex transform ---
    {
        float ri[9], ro[9], ti[3], to[3];
#pragma unroll
        for (int i = 0; i < 9; i++) { ri[i] = __ldg(R_in + i); ro[i] = __ldg(R_out + i); }
#pragma unroll
        for (int i = 0; i < 3; i++) { ti[i] = __ldg(T_in + i); to[i] = __ldg(T_out + i); }
        const float SCALE = 0.57735026918962576451f;   // tan(30deg)
        const float SINV  = 1.7320508075688772935f;    // 1/SCALE
        for (int v = tid; v < NVERT; v += NTH) {
            float xs = -1.0f + (float)(v % 17) * 0.125f;
            float ys = -1.0f + (float)(v / 17) * 0.125f;
            float gx = (xs + __ldg(xy_off + 2 * v)) * SCALE;
            float gy = (ys + __ldg(xy_off + 2 * v + 1)) * SCALE;
            float zg = __ldg(z_grid + v);
            float sx = gx * zg, sy = gy * zg, sz = zg;
            float p0 = sx - ti[0], p1 = sy - ti[1], p2 = sz - ti[2];
            float w0 = ri[0] * p0 + ri[1] * p1 + ri[2] * p2;
            float w1 = ri[3] * p0 + ri[4] * p1 + ri[5] * p2;
            float w2 = ri[6] * p0 + ri[7] * p1 + ri[8] * p2;
            float vx = ro[0] * w0 + ro[3] * w1 + ro[6] * w2 + to[0];
            float vy = ro[1] * w0 + ro[4] * w1 + ro[7] * w2 + to[1];
            float vz = ro[2] * w0 + ro[5] * w1 + ro[8] * w2 + to[2];
            float zden = (vz >= 0.0f) ? fmaxf(vz, 0.01f) : fminf(vz, -0.01f);
            float rz = __frcp_rn(zden);
            s_vx[v] = SINV * vx * rz;
            s_vy[v] = SINV * vy * rz;
            s_vz[v] = vz;
        }
    }
    __syncthreads();

    // --- face setup + order-preserving tile compaction ---
    const float M = 0.0105f;
    int total = 0;
#pragma unroll
    for (int c = 0; c < 2; c++) {
        int f = c * NTH + tid;
        int i0, i1, i2;
        face_vids(f, i0, i1, i2);
        float ax = s_vx[i0], ay = s_vy[i0], z0 = s_vz[i0];
        float bx = s_vx[i1], by = s_vy[i1], z1 = s_vz[i1];
        float cx = s_vx[i2], cy = s_vy[i2], z2 = s_vz[i2];
        float ymn = fminf(ay, fminf(by, cy)) - M;
        float ymx = fmaxf(ay, fmaxf(by, cy)) + M;
        float xmn = fminf(ax, fminf(bx, cx)) - M;
        float xmx = fmaxf(ax, fmaxf(bx, cx)) + M;
        bool ov = (xmn <= pxhi) && (xmx >= pxlo) && (ymn <= pyhi) && (ymx >= pylo);

        unsigned m = __ballot_sync(0xffffffffu, ov);
        if (lane == 0) s_wc[wid] = __popc(m);
        __syncthreads();
        int pos = total + __popc(m & ((1u << lane) - 1u));
#pragma unroll
        for (int w = 0; w < 8; w++) {
            if (w < wid) pos += s_wc[w];
            total += s_wc[w];
        }
        if (ov && pos < MAXC) {
            float area = (bx - ax) * (cy - ay) - (by - ay) * (cx - ax);
            float area_s = (fabsf(area) < 1e-8f) ? 1e-8f : area;
            float dabx = bx - ax, daby = by - ay;
            float dbcx = cx - bx, dbcy = cy - by;
            float dcax = ax - cx, dcay = ay - cy;
            float Lab = fmaxf(dabx * dabx + daby * daby, 1e-12f);
            float Lbc = fmaxf(dbcx * dbcx + dbcy * dbcy, 1e-12f);
            float Lca = fmaxf(dcax * dcax + dcay * dcay, 1e-12f);
            s_bb[pos] = make_float4(xmn, xmx, ymn, ymx);
            s_A[pos]  = make_float4(ax, ay, z0, __frcp_rn(area_s));
            s_B[pos]  = make_float4(bx, by, z1, __frcp_rn(Lab));
            s_C[pos]  = make_float4(cx, cy, z2, __frcp_rn(Lbc));
            s_E[pos]  = make_float4(__frcp_rn(Lca), z1 * z2, z0 * z2, z0 * z1);
            s_vi[pos] = make_int4(i0, i1, i2, 0);
        }
        __syncthreads();
    }
    if (total > MAXC) total = MAXC;

    // --- selection: 4-way strided; u64 keys (z_bits<<32 | idx); count valid ---
    unsigned long long kk[KF];
#pragma unroll
    for (int k = 0; k < KF; k++) kk[k] = KEY_INVALID;
    int cnt = 0;

    for (int i = sub; i < total; i += 4) {
        float4 bb = s_bb[i];
        if (px < bb.x || px > bb.y || py < bb.z || py > bb.w) continue;
        float zpix;
        if (eval_sel(px, py, s_A[i], s_B[i], s_C[i], s_E[i], zpix)) {
            cnt++;
            unsigned long long key =
                ((unsigned long long)__float_as_uint(zpix) << 32) | (unsigned)i;
            if (key < kk[KF - 1]) {
#pragma unroll
                for (int j = 0; j < KF; j++) {
                    if (key < kk[j]) {
                        unsigned long long t = kk[j]; kk[j] = key; key = t;
                    }
                }
            }
        }
    }

    // --- quad totals: valid count and zmax (max zinv == zinv of global min z,
    //     always in the top-8, so the max over ALL valid equals max over top-8) ---
    const float R99 = 0.010101010101010102f;
    float zmax_l = 1e-10f;
#pragma unroll
    for (int k = 0; k < KF; k++) {
        unsigned zb = (unsigned)(kk[k] >> 32);
        if (zb != 0xFFFFFFFFu)
            zmax_l = fmaxf(zmax_l, (100.0f - __uint_as_float(zb)) * R99);
    }
    int cnt_t = cnt;
    float zmax = zmax_l;
#pragma unroll
    for (int d = 1; d <= 2; d <<= 1) {
        cnt_t += __shfl_xor_sync(0xffffffffu, cnt_t, d);
        zmax = fmaxf(zmax, __shfl_xor_sync(0xffffffffu, zmax, d));
    }
    float delta = __expf((1e-10f - zmax) * 1e4f);

    // --- shading accumulators ---
    float sw = 0.0f, sr = 0.0f, sg = 0.0f, sb = 0.0f, sd = 0.0f, ap = 1.0f;

    auto shade = [&](unsigned long long key) {
        int f = (int)(unsigned)key;
        float zsel = __uint_as_float((unsigned)(key >> 32));
        float sdist, bn0, bn1, bn2;
        eval_face(px, py, s_A[f], s_B[f], s_C[f], s_E[f], sdist, bn0, bn1, bn2);
        int4 vi = s_vi[f];
        float u0 = 1.0f - (float)(vi.x % 17) * 0.0625f, vc0 = (float)(vi.x / 17) * 0.0625f;
        float u1 = 1.0f - (float)(vi.y % 17) * 0.0625f, vc1 = (float)(vi.y / 17) * 0.0625f;
        float u2 = 1.0f - (float)(vi.z % 17) * 0.0625f, vc2 = (float)(vi.z / 17) * 0.0625f;
        float uu = bn0 * u0 + bn1 * u1 + bn2 * u2;
        float vv = bn0 * vc0 + bn1 * vc1 + bn2 * vc2;
        float tx2 = uu * 127.0f;
        float ty2 = (1.0f - vv) * 127.0f;
        float x0f = fminf(fmaxf(floorf(tx2), 0.0f), 127.0f);
        float y0f = fminf(fmaxf(floorf(ty2), 0.0f), 127.0f);
        int x0 = (int)x0f, y0 = (int)y0f;
        int x1 = min(x0 + 1, 127), y1 = min(y0 + 1, 127);
        float wx = tx2 - x0f, wy = ty2 - y0f;
        const float* p00 = tex + (y0 * IMGS + x0) * 3;
        const float* p01 = tex + (y0 * IMGS + x1) * 3;
        const float* p10 = tex + (y1 * IMGS + x0) * 3;
        const float* p11 = tex + (y1 * IMGS + x1) * 3;
        float omwx = 1.0f - wx, omwy = 1.0f - wy;
        float cr = omwy * (omwx * __ldg(p00 + 0) + wx * __ldg(p01 + 0)) +
                   wy   * (omwx * __ldg(p10 + 0) + wx * __ldg(p11 + 0));
        float cg = omwy * (omwx * __ldg(p00 + 1) + wx * __ldg(p01 + 1)) +
                   wy   * (omwx * __ldg(p10 + 1) + wx * __ldg(p11 + 1));
        float cb = omwy * (omwx * __ldg(p00 + 2) + wx * __ldg(p01 + 2)) +
                   wy   * (omwx * __ldg(p10 + 2) + wx * __ldg(p11 + 2));
        float pr  = __frcp_rn(1.0f + __expf(sdist * 1e4f));
        float zin = (100.0f - zsel) * R99;
        float w   = pr * __expf((zin - zmax) * 1e4f);
        sw += w;
        sr += w * cr;
        sg += w * cg;
        sb += w * cb;
        sd += w * zsel;
        ap *= (1.0f - pr);
    };

    if (cnt_t <= KF) {
        // FAST PATH (common): all valid faces are the top-8 set. Each lane
        // shades its own finds. No merge needed.
#pragma unroll
        for (int k = 0; k < KF; k++) {
            if (kk[k] == KEY_INVALID) break;
            shade(kk[k]);
        }
    } else {
        // SLOW PATH (rare): proper top-8 via 2-round merge (R8-proven).
        // Round 1 (xor 1): full merge + bitonic cleanup.
        {
            unsigned long long bk[KF];
#pragma unroll
            for (int i = 0; i < KF; i++)
                bk[i] = __shfl_xor_sync(0xffffffffu, kk[i], 1);
            unsigned long long ck[KF];
#pragma unroll
            for (int i = 0; i < KF; i++)
                ck[i] = u64min(kk[i], bk[KF - 1 - i]);
#pragma unroll
            for (int d2 = 4; d2 >= 1; d2 >>= 1) {
#pragma unroll
                for (int i = 0; i < KF; i++) {
                    if ((i & d2) == 0) {
                        int j = i + d2;
                        unsigned long long lo = u64min(ck[i], ck[j]);
                        unsigned long long hi = (ck[i] < ck[j]) ? ck[j] : ck[i];
                        ck[i] = lo; ck[j] = hi;
                    }
                }
            }
#pragma unroll
            for (int i = 0; i < KF; i++) kk[i] = ck[i];
        }
        // Round 2 (xor 2): min-merge only; lanes 2,3 hold reverse(set).
        {
            unsigned long long bk[KF];
#pragma unroll
            for (int i = 0; i < KF; i++)
                bk[i] = __shfl_xor_sync(0xffffffffu, kk[i], 2);
#pragma unroll
            for (int i = 0; i < KF; i++)
                kk[i] = u64min(kk[i], bk[KF - 1 - i]);
        }
        // Reversal-aware assignment: lane0:{0,4} lane1:{1,5} lane2:{5,1} lane3:{4,0}
        unsigned long long ks0 =
            (sub == 0) ? kk[0] : (sub == 1) ? kk[1] : (sub == 2) ? kk[5] : kk[4];
        unsigned long long ks1 =
            (sub == 0) ? kk[4] : (sub == 1) ? kk[5] : (sub == 2) ? kk[1] : kk[0];
        if (ks0 != KEY_INVALID) shade(ks0);
        if (ks1 != KEY_INVALID) shade(ks1);
    }

    // --- quad butterfly reduction ---
#pragma unroll
    for (int d = 1; d <= 2; d <<= 1) {
        sw += __shfl_xor_sync(0xffffffffu, sw, d);
        sr += __shfl_xor_sync(0xffffffffu, sr, d);
        sg += __shfl_xor_sync(0xffffffffu, sg, d);
        sb += __shfl_xor_sync(0xffffffffu, sb, d);
        sd += __shfl_xor_sync(0xffffffffu, sd, d);
        ap *= __shfl_xor_sync(0xffffffffu, ap, d);
    }
    float rdenom = __frcp_rn(sw + delta);

    int o = (iy * IMGS + ix) * 5;
    if (sub == 0) {
        out[o + 0] = sr * rdenom;
        out[o + 4] = (sd + delta * 100.0f) * rdenom;
    } else if (sub == 1) {
        out[o + 1] = sg * rdenom;
    } else if (sub == 2) {
        out[o + 2] = sb * rdenom;
    } else {
        out[o + 3] = 1.0f - ap;
    }
}

extern "C" void kernel_launch(void* const* d_in, const int* in_sizes, int n_in,
                              void* d_out, int out_size) {
    (void)in_sizes; (void)n_in; (void)out_size;
    nvp_kernel<<<256, NTH>>>(
        (const float*)d_in[0],   // xy_offset (1,289,2)
        (const float*)d_in[1],   // z_grid    (1,289,1)
        (const float*)d_in[2],   // rgb_in    (1,128,128,3)
        (const float*)d_in[3],   // R_in      (1,3,3)
        (const float*)d_in[4],   // T_in      (1,3)
        (const float*)d_in[5],   // R_out     (1,3,3)
        (const float*)d_in[6],   // T_out     (1,3)
        (float*)d_out);          // (1,128,128,5) float32
}